// round 17
// baseline (speedup 1.0000x reference)
#include <cuda_runtime.h>
#include <cuda_bf16.h>
#include <cstdint>

#define HIDDEN 32
#define FF 40
#define TSTEPS 512
#define BATCH 16384
#define THREADS 256        /* 8 warps x 16 rows = 128 elements per block */
#define EPB 128

typedef unsigned long long u64;
typedef unsigned int u32;

// sigmoid via ex2/rcp approx (proven rel_err ~2e-6 with bf16-split MMA)
__device__ __forceinline__ float sigm(float x) {
    float e, r;
    asm("ex2.approx.ftz.f32 %0,%1;" : "=f"(e) : "f"(x * -1.4426950408889634f));
    asm("rcp.approx.ftz.f32 %0,%1;" : "=f"(r) : "f"(1.0f + e));
    return r;
}
__device__ __forceinline__ u32 bfbits(float x) {       // rn bf16, low 16 bits
    return (u32)__bfloat16_as_ushort(__float2bfloat16(x));
}
__device__ __forceinline__ float bf2f(u32 b) { return __uint_as_float(b << 16); }

// m16n8k16 bf16 mma, accumulate in place
__device__ __forceinline__ void mma_acc(float* d, u32 a0, u32 a1, u32 a2, u32 a3,
                                        u32 b0, u32 b1) {
    asm volatile(
        "mma.sync.aligned.m16n8k16.row.col.f32.bf16.bf16.f32 "
        "{%0,%1,%2,%3}, {%4,%5,%6,%7}, {%8,%9}, {%0,%1,%2,%3};"
        : "+f"(d[0]), "+f"(d[1]), "+f"(d[2]), "+f"(d[3])
        : "r"(a0), "r"(a1), "r"(a2), "r"(a3), "r"(b0), "r"(b1));
}
// first mma of a chain: C = 0 (no zero-init movs needed)
__device__ __forceinline__ void mma_zro(float* d, u32 a0, u32 a1, u32 a2, u32 a3,
                                        u32 b0, u32 b1, float zz) {
    asm volatile(
        "mma.sync.aligned.m16n8k16.row.col.f32.bf16.bf16.f32 "
        "{%0,%1,%2,%3}, {%4,%5,%6,%7}, {%8,%9}, {%10,%10,%10,%10};"
        : "=f"(d[0]), "=f"(d[1]), "=f"(d[2]), "=f"(d[3])
        : "r"(a0), "r"(a1), "r"(a2), "r"(a3), "r"(b0), "r"(b1), "f"(zz));
}

// weight value (bf16 bits) at fused-K position k, column n
__device__ u32 wv16(int k, int n, const float* sWf, const float* sBf, const float* sUa) {
    float v; bool lo = false;
    if      (k <  40)  v = sWf[k * 80 + n];                 // s_hi * W_hi
    else if (k <  80){ v = sWf[(k - 40) * 80 + n]; lo = 1; }// s_hi * W_lo
    else if (k < 120)  v = sWf[(k - 80) * 80 + n];          // s_lo * W_hi
    else if (k == 120) v = sBf[n];                          // 1 * Bf_hi
    else if (k == 121){ v = sBf[n]; lo = 1; }               // 1 * Bf_lo
    else if (k == 122) v = sUa[n];                          // u_hi * U_hi
    else if (k == 123){ v = sUa[n]; lo = 1; }               // u_hi * U_lo
    else if (k == 124) v = sUa[n];                          // u_lo * U_hi
    else return 0u;
    u32 hb = bfbits(v);
    if (!lo) return hb;
    return bfbits(v - bf2f(hb));
}

// ---- pack A fragments from z_cur and issue the 80-mma chain into z_new ----
__device__ __forceinline__ void pack_mma(
    const float (&zc)[10][4], float (&zn)[10][4],
    float un0, float un1, int tig, int lane, const u64* __restrict__ sBfrag)
{
    u32 ph[5][2], pl[5][2];
    #pragma unroll
    for (int j = 0; j < 5; j++) {
        #pragma unroll
        for (int r = 0; r < 2; r++) {
            float sa = sigm(zc[j][2 * r]);
            float sb = sigm(zc[j][2 * r + 1]);
            u32 ha = bfbits(sa), hb = bfbits(sb);
            ph[j][r] = ha | (hb << 16);
            u32 la = bfbits(sa - bf2f(ha)), lb = bfbits(sb - bf2f(hb));
            pl[j][r] = la | (lb << 16);
        }
    }
    u32 q7r0, q7r1;
    {
        u32 uh0 = bfbits(un0), uh1 = bfbits(un1);
        u32 ul0 = bfbits(un0 - bf2f(uh0)), ul1 = bfbits(un1 - bf2f(uh1));
        q7r0 = (tig == 0) ? 0x3F803F80u
             : (tig == 1) ? (uh0 | (uh0 << 16))
             : (tig == 2) ? ul0 : 0u;
        q7r1 = (tig == 0) ? 0x3F803F80u
             : (tig == 1) ? (uh1 | (uh1 << 16))
             : (tig == 2) ? ul1 : 0u;
    }
    // A slices q=0..7 (validated R16 mapping)
    u32 A[8][4];
    A[0][0] = ph[0][0]; A[0][1] = ph[0][1]; A[0][2] = ph[1][0]; A[0][3] = ph[1][1];
    A[1][0] = ph[2][0]; A[1][1] = ph[2][1]; A[1][2] = ph[3][0]; A[1][3] = ph[3][1];
    A[2][0] = ph[4][0]; A[2][1] = ph[4][1]; A[2][2] = ph[0][0]; A[2][3] = ph[0][1];
    A[3][0] = ph[1][0]; A[3][1] = ph[1][1]; A[3][2] = ph[2][0]; A[3][3] = ph[2][1];
    A[4][0] = ph[3][0]; A[4][1] = ph[3][1]; A[4][2] = ph[4][0]; A[4][3] = ph[4][1];
    A[5][0] = pl[0][0]; A[5][1] = pl[0][1]; A[5][2] = pl[1][0]; A[5][3] = pl[1][1];
    A[6][0] = pl[2][0]; A[6][1] = pl[2][1]; A[6][2] = pl[3][0]; A[6][3] = pl[3][1];
    A[7][0] = pl[4][0]; A[7][1] = pl[4][1]; A[7][2] = q7r0;     A[7][3] = q7r1;

    #pragma unroll
    for (int q = 0; q < 8; q++) {
        #pragma unroll
        for (int j = 0; j < 10; j++) {
            u64 b = sBfrag[(q * 10 + j) * 32 + lane];
            if (q == 0)
                mma_zro(zn[j], A[q][0], A[q][1], A[q][2], A[q][3],
                        (u32)b, (u32)(b >> 32), 0.0f);
            else
                mma_acc(zn[j], A[q][0], A[q][1], A[q][2], A[q][3],
                        (u32)b, (u32)(b >> 32));
        }
    }
}

// ---- output head from OLD z (independent of in-flight mma) ----
__device__ __forceinline__ void out_head(
    const float (&zc)[10][4], const float (&wo0)[5], const float (&wo1)[5],
    float bias_o, int tig, float* __restrict__ op0, float* __restrict__ op1, int t)
{
    float a0 = 0.0f, a1 = 0.0f;
    #pragma unroll
    for (int jj = 0; jj < 5; jj++) {
        int j = jj + 5;
        a0 = fmaf(sigm(zc[j][0]), wo0[jj], a0);
        a0 = fmaf(sigm(zc[j][1]), wo1[jj], a0);
        a1 = fmaf(sigm(zc[j][2]), wo0[jj], a1);
        a1 = fmaf(sigm(zc[j][3]), wo1[jj], a1);
    }
    a0 += __shfl_xor_sync(0xffffffffu, a0, 1);
    a0 += __shfl_xor_sync(0xffffffffu, a0, 2);
    a1 += __shfl_xor_sync(0xffffffffu, a1, 1);
    a1 += __shfl_xor_sync(0xffffffffu, a1, 2);
    if (tig == 0) { op0[t] = a0 + bias_o; op1[t] = a1 + bias_o; }
}

__global__ void __launch_bounds__(THREADS, 1) rnn_mma2_kernel(
    const float* __restrict__ inp,
    const float* __restrict__ W1hh, const float* __restrict__ b1hh,
    const float* __restrict__ W2hh, const float* __restrict__ b2hh,
    const float* __restrict__ W1ho, const float* __restrict__ b1ho,
    const float* __restrict__ W2ho, const float* __restrict__ b2ho,
    float* __restrict__ out)
{
    __shared__ float sWf[40 * 80];     // fused Wf[kk][n]
    __shared__ u64   sBfrag[80 * 32];  // pre-packed B fragments [q*10+j][lane]
    __shared__ float sU[80], sB0[80], sBf[80], sW2ho[FF];

    const int tid = threadIdx.x;

    // ---- init: fused Wf[kk][n] = sum_i W2hh[kk][i] * W1x[i][col] ----
    for (int idx = tid; idx < 40 * 80; idx += THREADS) {
        int kk = idx / 80, n = idx % 80;
        const float* W1p = (n < FF) ? (W1hh + n) : (W1ho + (n - FF));
        const float* W2p = W2hh + kk * HIDDEN;
        float acc = 0.0f;
        #pragma unroll
        for (int i = 0; i < HIDDEN; i++) acc += W2p[i] * W1p[i * FF];
        sWf[idx] = acc;
    }
    for (int n = tid; n < 80; n += THREADS) {
        const float* W1p = (n < FF) ? (W1hh + n) : (W1ho + (n - FF));
        float b1 = (n < FF) ? b1hh[n] : b1ho[n - FF];
        float acc = 0.0f;
        #pragma unroll
        for (int i = 0; i < HIDDEN; i++) acc += b2hh[i] * W1p[i * FF];
        sB0[n] = b1;                 // t=0 bias (h0 = 0 exactly)
        sBf[n] = b1 + acc;           // recurrent bias (absorbs b2hh @ W1[0:32])
        sU[n]  = W1p[32 * FF];       // input-row weights
    }
    for (int n = tid; n < FF; n += THREADS) sW2ho[n] = W2ho[n];
    const float bias_o = b2ho[0];
    __syncthreads();

    // ---- pack B fragments ----
    for (int idx = tid; idx < 80 * 32; idx += THREADS) {
        int tile = idx >> 5, ln = idx & 31;
        int q = tile / 10, j = tile % 10;
        int n = 8 * j + (ln >> 2);
        int k0 = 16 * q + (ln & 3) * 2;
        u32 b0 = wv16(k0, n, sWf, sBf, sU) | (wv16(k0 + 1, n, sWf, sBf, sU) << 16);
        u32 b1 = wv16(k0 + 8, n, sWf, sBf, sU) | (wv16(k0 + 9, n, sWf, sBf, sU) << 16);
        sBfrag[idx] = (u64)b0 | ((u64)b1 << 32);
    }
    __syncthreads();

    const int lane = tid & 31;
    const int w    = tid >> 5;
    const int tig  = lane & 3;
    const int grp  = lane >> 2;
    const int e0   = blockIdx.x * EPB + w * 16 + grp;
    const int e1   = e0 + 8;
    const float* __restrict__ ip0 = inp + (size_t)e0 * TSTEPS;
    const float* __restrict__ ip1 = inp + (size_t)e1 * TSTEPS;
    float* __restrict__ op0 = out + (size_t)e0 * TSTEPS;
    float* __restrict__ op1 = out + (size_t)e1 * TSTEPS;

    float wo0[5], wo1[5];
    #pragma unroll
    for (int jj = 0; jj < 5; jj++) {
        wo0[jj] = sW2ho[8 * jj + tig * 2];
        wo1[jj] = sW2ho[8 * jj + tig * 2 + 1];
    }

    // ---- t=0: z = u0*U + B0 (exact fp32; h0 = 0) ----
    float zA[10][4], zB[10][4];
    {
        float u00 = ip0[0], u01 = ip1[0];
        #pragma unroll
        for (int j = 0; j < 10; j++) {
            int c = 8 * j + tig * 2;
            float Uc = sU[c], Uc1 = sU[c + 1], Bc = sB0[c], Bc1 = sB0[c + 1];
            zA[j][0] = fmaf(u00, Uc, Bc);  zA[j][1] = fmaf(u00, Uc1, Bc1);
            zA[j][2] = fmaf(u01, Uc, Bc);  zA[j][3] = fmaf(u01, Uc1, Bc1);
        }
    }

    float un0 = ip0[1], un1 = ip1[1];   // u for producing z_1

    // 2x-unrolled pipeline: pack+mma FIRST (tensor in flight), then out-head
    // from the OLD z (MUFU/FMA/STG execute under the HMMA shadow).
    #pragma unroll 1
    for (int tt = 0; tt < TSTEPS / 2; tt++) {
        const int t0 = 2 * tt;
        // even step: zA -> zB  (produce z_{t0+1}); out(t0) from zA
        pack_mma(zA, zB, un0, un1, tig, lane, sBfrag);
        {   // prefetch u_{t0+2} for the odd pack
            int tn = (t0 + 2 < TSTEPS) ? (t0 + 2) : (TSTEPS - 1);
            un0 = ip0[tn]; un1 = ip1[tn];
        }
        out_head(zA, wo0, wo1, bias_o, tig, op0, op1, t0);

        // odd step: zB -> zA (produce z_{t0+2}), skipped on final iteration
        if (tt < TSTEPS / 2 - 1) {
            pack_mma(zB, zA, un0, un1, tig, lane, sBfrag);
            int tn = (t0 + 3 < TSTEPS) ? (t0 + 3) : (TSTEPS - 1);
            un0 = ip0[tn]; un1 = ip1[tn];
        }
        out_head(zB, wo0, wo1, bias_o, tig, op0, op1, t0 + 1);
    }
}

extern "C" void kernel_launch(void* const* d_in, const int* in_sizes, int n_in,
                              void* d_out, int out_size) {
    const float* inp  = (const float*)d_in[0];
    const float* W1hh = (const float*)d_in[1];
    const float* b1hh = (const float*)d_in[2];
    const float* W2hh = (const float*)d_in[3];
    const float* b2hh = (const float*)d_in[4];
    const float* W1ho = (const float*)d_in[5];
    const float* b1ho = (const float*)d_in[6];
    const float* W2ho = (const float*)d_in[7];
    const float* b2ho = (const float*)d_in[8];
    float* out = (float*)d_out;

    dim3 grid(BATCH / EPB);   // 128 blocks x 256 threads (8 independent warps each)
    dim3 block(THREADS);
    rnn_mma2_kernel<<<grid, block>>>(inp, W1hh, b1hh, W2hh, b2hh,
                                     W1ho, b1ho, W2ho, b2ho, out);
}